// round 16
// baseline (speedup 1.0000x reference)
#include <cuda_runtime.h>
#include <cmath>

// ----------------------------------------------------------------------------
// Model dims
//   L=12, H=768, NH=12, DN=32, DR=32, DV=64, R=512, E=8, K=2, I=256, SI=1024
//   B=2, S=512, V=64  -> T = B*S = 1024 tokens
// ----------------------------------------------------------------------------

// ---------------- device scratch (static, allocation-free) ----------------
__device__ float d_h   [1024*768];        // residual stream
__device__ float d_x   [1024*768];        // rms-normed activations
__device__ float d_q   [1024*768];        // q per token: [h][64] (nope||pe)
__device__ float d_kva [1024*544];        // c_kv(512) || k_pe(32)
__device__ float d_ckv [1024*512];        // normed c_kv
__device__ float d_kv  [1024*1152];       // per token: [h][96] (k_nope(32)||v(64))
__device__ float d_keys[1024*768];        // per token: [h][64] (k_nope||roped k_pe)
__device__ float d_scores[2*12*512*512];  // [b][h][q][k]
__device__ float d_attn[1024*768];        // [t][h*64+dv]
__device__ float d_t1  [1024*1024];       // shared-FFN gate
__device__ float d_t2  [1024*1024];       // shared-FFN up / then ys output
__device__ float d_g   [2048*256];        // expert hidden per token-slot
__device__ float d_eo  [2048*768];        // expert output per token-slot (pre-weighted)
__device__ float d_gatew[2048];           // normalized top-2 weights per token-slot
__device__ int   d_cnt [8];
__device__ int   d_list[8*1024];          // per-expert: entry = token*2 + slot

// ----------------------------------------------------------------------------
// Generic NT SGEMM:  C[m,n] (=, +=) alpha * sum_k A[m,k]*B[n,k]  (+ bias[n])
// 64x64 tile, TK=16, 256 threads, 4x4 per thread. K must be a multiple of 16.
// Batched via blockIdx.z decoded as (bb = z/zdiv, hh = z%zdiv) with strides.
// ----------------------------------------------------------------------------
__global__ void sgemm_nt(const float* __restrict__ A, int lda,
                         const float* __restrict__ B, int ldb,
                         float* __restrict__ C, int ldc,
                         int M, int N, int K, float alpha, int mode,
                         const float* __restrict__ bias,
                         int zdiv, long long sAb, long long sAh,
                         long long sBb, long long sBh,
                         long long sCb, long long sCh)
{
    int z = blockIdx.z;
    int bb = z / zdiv, hh = z % zdiv;
    A += bb * sAb + hh * sAh;
    B += bb * sBb + hh * sBh;
    C += bb * sCb + hh * sCh;

    __shared__ __align__(16) float As[16][68];
    __shared__ __align__(16) float Bs[16][68];

    int n0 = blockIdx.x * 64, m0 = blockIdx.y * 64;
    int tid = threadIdx.x;
    int lk = tid & 15, lr = tid >> 4;
    int ty = tid >> 4, tx = tid & 15;

    float acc[4][4] = {};
    for (int k0 = 0; k0 < K; k0 += 16) {
        #pragma unroll
        for (int i = 0; i < 4; i++) {
            int r = lr + i * 16;
            int gm = m0 + r;
            As[lk][r] = (gm < M) ? A[(size_t)gm * lda + k0 + lk] : 0.f;
            int gn = n0 + r;
            Bs[lk][r] = (gn < N) ? B[(size_t)gn * ldb + k0 + lk] : 0.f;
        }
        __syncthreads();
        #pragma unroll
        for (int kk = 0; kk < 16; kk++) {
            float4 av = *reinterpret_cast<const float4*>(&As[kk][ty * 4]);
            float4 bv = *reinterpret_cast<const float4*>(&Bs[kk][tx * 4]);
            float a[4] = {av.x, av.y, av.z, av.w};
            float b[4] = {bv.x, bv.y, bv.z, bv.w};
            #pragma unroll
            for (int i = 0; i < 4; i++)
                #pragma unroll
                for (int j = 0; j < 4; j++)
                    acc[i][j] += a[i] * b[j];
        }
        __syncthreads();
    }
    #pragma unroll
    for (int i = 0; i < 4; i++) {
        int m = m0 + ty * 4 + i;
        if (m >= M) continue;
        #pragma unroll
        for (int j = 0; j < 4; j++) {
            int n = n0 + tx * 4 + j;
            if (n >= N) continue;
            float v = acc[i][j] * alpha;
            if (bias) v += bias[n];
            if (mode) C[(size_t)m * ldc + n] += v;
            else      C[(size_t)m * ldc + n]  = v;
        }
    }
}

// ----------------------------------------------------------------------------
// NN SGEMM:  C[m,n] = sum_k A[m,k]*B[k,n]   (used for probs @ V)
// ----------------------------------------------------------------------------
__global__ void sgemm_nn(const float* __restrict__ A, int lda,
                         const float* __restrict__ B, int ldb,
                         float* __restrict__ C, int ldc,
                         int M, int N, int K,
                         int zdiv, long long sAb, long long sAh,
                         long long sBb, long long sBh,
                         long long sCb, long long sCh)
{
    int z = blockIdx.z;
    int bb = z / zdiv, hh = z % zdiv;
    A += bb * sAb + hh * sAh;
    B += bb * sBb + hh * sBh;
    C += bb * sCb + hh * sCh;

    __shared__ __align__(16) float As[16][68];
    __shared__ __align__(16) float Bs[16][68];

    int n0 = blockIdx.x * 64, m0 = blockIdx.y * 64;
    int tid = threadIdx.x;
    int lk = tid & 15, lr = tid >> 4;
    int bc = tid & 63, bk = tid >> 6;
    int ty = tid >> 4, tx = tid & 15;

    float acc[4][4] = {};
    for (int k0 = 0; k0 < K; k0 += 16) {
        #pragma unroll
        for (int i = 0; i < 4; i++) {
            int r = lr + i * 16;
            int gm = m0 + r;
            As[lk][r] = (gm < M) ? A[(size_t)gm * lda + k0 + lk] : 0.f;
        }
        #pragma unroll
        for (int i = 0; i < 4; i++) {
            int kk = bk + i * 4;
            int gn = n0 + bc;
            Bs[kk][bc] = (gn < N) ? B[(size_t)(k0 + kk) * ldb + gn] : 0.f;
        }
        __syncthreads();
        #pragma unroll
        for (int kk = 0; kk < 16; kk++) {
            float4 av = *reinterpret_cast<const float4*>(&As[kk][ty * 4]);
            float4 bv = *reinterpret_cast<const float4*>(&Bs[kk][tx * 4]);
            float a[4] = {av.x, av.y, av.z, av.w};
            float b[4] = {bv.x, bv.y, bv.z, bv.w};
            #pragma unroll
            for (int i = 0; i < 4; i++)
                #pragma unroll
                for (int j = 0; j < 4; j++)
                    acc[i][j] += a[i] * b[j];
        }
        __syncthreads();
    }
    #pragma unroll
    for (int i = 0; i < 4; i++) {
        int m = m0 + ty * 4 + i;
        if (m >= M) continue;
        #pragma unroll
        for (int j = 0; j < 4; j++) {
            int n = n0 + tx * 4 + j;
            if (n >= N) continue;
            C[(size_t)m * ldc + n] = acc[i][j];
        }
    }
}

// ----------------------------------------------------------------------------
// RMSNorm: out[t, 0..w) = in[t]/sqrt(mean(in^2)+1e-6) * weight
// ----------------------------------------------------------------------------
__global__ void rmsnorm_kernel(const float* __restrict__ in, int istride,
                               float* __restrict__ out, int ostride,
                               int width, const float* __restrict__ w)
{
    int t = blockIdx.x;
    const float* xi = in + (size_t)t * istride;
    float* xo = out + (size_t)t * ostride;
    __shared__ float red[256];
    float ss = 0.f;
    for (int c = threadIdx.x; c < width; c += 256) { float v = xi[c]; ss += v * v; }
    red[threadIdx.x] = ss;
    __syncthreads();
    for (int o = 128; o > 0; o >>= 1) {
        if (threadIdx.x < o) red[threadIdx.x] += red[threadIdx.x + o];
        __syncthreads();
    }
    float inv = 1.f / sqrtf(red[0] / (float)width + 1e-6f);
    for (int c = threadIdx.x; c < width; c += 256)
        xo[c] = xi[c] * inv * w[c];
}

// ----------------------------------------------------------------------------
// RoPE (q in-place) + build keys buffer [t][h][ k_nope(32) || roped k_pe(32) ]
// inv_freq[d] = 10000^(-d/32), rot_half over halves of 16.
// POSITION is the within-batch sequence index: pos = t % 512 (t = b*512 + s).
// ----------------------------------------------------------------------------
__global__ void rope_keys_kernel(float* __restrict__ q,
                                 const float* __restrict__ kva,
                                 const float* __restrict__ kv,
                                 float* __restrict__ keys)
{
    int t = blockIdx.x;
    int pos = t & 511;   // sequence position within the batch (B=2, S=512)
    __shared__ float cs[32], sn[32], kr[32];
    if (threadIdx.x < 32) {
        int d = threadIdx.x;
        double f = pow(10000.0, -(double)d / 32.0);
        double ang = (double)pos * f;
        cs[d] = (float)cos(ang);
        sn[d] = (float)sin(ang);
    }
    __syncthreads();
    if (threadIdx.x < 32) {
        int d = threadIdx.x;
        const float* kp = kva + (size_t)t * 544 + 512;
        float rot = (d < 16) ? -kp[d + 16] : kp[d - 16];
        kr[d] = kp[d] * cs[d] + rot * sn[d];
    }
    if (threadIdx.x < 192) {
        int h = threadIdx.x / 16, d = threadIdx.x % 16;
        float* qp = q + (size_t)t * 768 + h * 64 + 32;
        float a = qp[d], b = qp[d + 16];
        qp[d]      = a * cs[d]      - b * sn[d];
        qp[d + 16] = b * cs[d + 16] + a * sn[d + 16];
    }
    __syncthreads();
    for (int i = threadIdx.x; i < 768; i += 256) {
        int h = i >> 6, d = i & 63;
        keys[(size_t)t * 768 + i] =
            (d < 32) ? kv[(size_t)t * 1152 + h * 96 + d] : kr[d - 32];
    }
}

// ----------------------------------------------------------------------------
// Causal row softmax over materialized scores. row = ((b*12+h)*512 + q)
// ----------------------------------------------------------------------------
__global__ void softmax_causal(float* __restrict__ sc)
{
    long long row = blockIdx.x;
    int q = (int)(row & 511);
    float* s = sc + row * 512;
    __shared__ float red[256];
    float mx = -3.4e38f;
    for (int k = threadIdx.x; k <= q; k += 256) mx = fmaxf(mx, s[k]);
    red[threadIdx.x] = mx;
    __syncthreads();
    for (int o = 128; o > 0; o >>= 1) {
        if (threadIdx.x < o) red[threadIdx.x] = fmaxf(red[threadIdx.x], red[threadIdx.x + o]);
        __syncthreads();
    }
    mx = red[0];
    __syncthreads();
    float sum = 0.f;
    for (int k = threadIdx.x; k <= q; k += 256) {
        float e = expf(s[k] - mx);
        s[k] = e;
        sum += e;
    }
    red[threadIdx.x] = sum;
    __syncthreads();
    for (int o = 128; o > 0; o >>= 1) {
        if (threadIdx.x < o) red[threadIdx.x] += red[threadIdx.x + o];
        __syncthreads();
    }
    float inv = 1.f / red[0];
    for (int k = threadIdx.x; k < 512; k += 256)
        s[k] = (k <= q) ? s[k] * inv : 0.f;
}

// ----------------------------------------------------------------------------
// Gate: logits = x @ gw.T (8), top-2, normalized weights, per-expert lists.
// softmax normalization cancels in topv/sum(topv) -> compute from logits.
// ----------------------------------------------------------------------------
__global__ void gate_kernel(const float* __restrict__ x,
                            const float* __restrict__ gw,
                            int* __restrict__ cnt, int* __restrict__ list,
                            float* __restrict__ wts)
{
    int t = blockIdx.x;
    __shared__ float xs[768];
    __shared__ float logits[8];
    for (int c = threadIdx.x; c < 768; c += 256) xs[c] = x[(size_t)t * 768 + c];
    __syncthreads();
    int warp = threadIdx.x >> 5, lane = threadIdx.x & 31;
    float acc = 0.f;
    for (int c = lane; c < 768; c += 32) acc += xs[c] * gw[warp * 768 + c];
    for (int o = 16; o > 0; o >>= 1) acc += __shfl_down_sync(0xffffffffu, acc, o);
    if (lane == 0) logits[warp] = acc;
    __syncthreads();
    if (threadIdx.x == 0) {
        int i0 = 0;
        for (int e = 1; e < 8; e++) if (logits[e] > logits[i0]) i0 = e;
        int i1 = (i0 == 0) ? 1 : 0;
        for (int e = 0; e < 8; e++) {
            if (e == i0) continue;
            if (logits[e] > logits[i1]) i1 = e;
        }
        float p0 = 1.f;                       // exp(l0 - l0)
        float p1 = expf(logits[i1] - logits[i0]);
        float s = p0 + p1;
        int pos0 = atomicAdd(&cnt[i0], 1);
        list[i0 * 1024 + pos0] = t * 2 + 0;
        wts[t * 2 + 0] = p0 / s;
        int pos1 = atomicAdd(&cnt[i1], 1);
        list[i1 * 1024 + pos1] = t * 2 + 1;
        wts[t * 2 + 1] = p1 / s;
    }
}

__global__ void zero_cnt_kernel(int* __restrict__ cnt)
{
    if (threadIdx.x < 8) cnt[threadIdx.x] = 0;
}

// ----------------------------------------------------------------------------
// Expert MLP stage 1 (dual gathered NT GEMM + silu-mul epilogue):
//   g[entry, n] = silu(x[tok]@w1[e].T) * (x[tok]@w3[e].T),  K=768, N=256
// ----------------------------------------------------------------------------
__global__ void expert_mlp1(const float* __restrict__ x,
                            const float* __restrict__ w1,
                            const float* __restrict__ w3,
                            const int* __restrict__ cnt,
                            const int* __restrict__ list,
                            float* __restrict__ g)
{
    int e = blockIdx.z;
    int me = cnt[e];
    int m0 = blockIdx.y * 64;
    if (m0 >= me) return;
    int n0 = blockIdx.x * 64;
    const int* lst = list + e * 1024;
    const float* W1 = w1 + (size_t)e * 256 * 768;
    const float* W3 = w3 + (size_t)e * 256 * 768;

    __shared__ __align__(16) float As[16][68];
    __shared__ __align__(16) float B1[16][68];
    __shared__ __align__(16) float B3[16][68];
    __shared__ int toks[64];

    if (threadIdx.x < 64) {
        int r = m0 + threadIdx.x;
        toks[threadIdx.x] = (r < me) ? lst[r] : -1;
    }
    __syncthreads();

    int tid = threadIdx.x;
    int lk = tid & 15, lr = tid >> 4;
    int ty = tid >> 4, tx = tid & 15;
    float a1[4][4] = {}, a3[4][4] = {};

    for (int k0 = 0; k0 < 768; k0 += 16) {
        #pragma unroll
        for (int i = 0; i < 4; i++) {
            int r = lr + i * 16;
            int ent = toks[r];
            As[lk][r] = (ent >= 0) ? x[(size_t)(ent >> 1) * 768 + k0 + lk] : 0.f;
            int gn = n0 + r;
            B1[lk][r] = W1[(size_t)gn * 768 + k0 + lk];
            B3[lk][r] = W3[(size_t)gn * 768 + k0 + lk];
        }
        __syncthreads();
        #pragma unroll
        for (int kk = 0; kk < 16; kk++) {
            float4 av  = *reinterpret_cast<const float4*>(&As[kk][ty * 4]);
            float4 b1v = *reinterpret_cast<const float4*>(&B1[kk][tx * 4]);
            float4 b3v = *reinterpret_cast<const float4*>(&B3[kk][tx * 4]);
            float a[4]  = {av.x,  av.y,  av.z,  av.w};
            float b1[4] = {b1v.x, b1v.y, b1v.z, b1v.w};
            float b3[4] = {b3v.x, b3v.y, b3v.z, b3v.w};
            #pragma unroll
            for (int i = 0; i < 4; i++)
                #pragma unroll
                for (int j = 0; j < 4; j++) {
                    a1[i][j] += a[i] * b1[j];
                    a3[i][j] += a[i] * b3[j];
                }
        }
        __syncthreads();
    }
    #pragma unroll
    for (int i = 0; i < 4; i++) {
        int r = ty * 4 + i;
        int ent = toks[r];
        if (ent < 0) continue;
        #pragma unroll
        for (int j = 0; j < 4; j++) {
            int n = n0 + tx * 4 + j;
            float va = a1[i][j];
            float sv = va / (1.f + expf(-va));
            g[(size_t)ent * 256 + n] = sv * a3[i][j];
        }
    }
}

// ----------------------------------------------------------------------------
// Expert MLP stage 2 (gathered NT GEMM, weighted scatter):
//   eo[entry, n] = wts[entry] * (g[entry]@w2[e].T),  K=256, N=768
// ----------------------------------------------------------------------------
__global__ void expert_mlp2(const float* __restrict__ g,
                            const float* __restrict__ w2,
                            const int* __restrict__ cnt,
                            const int* __restrict__ list,
                            const float* __restrict__ wts,
                            float* __restrict__ eo)
{
    int e = blockIdx.z;
    int me = cnt[e];
    int m0 = blockIdx.y * 64;
    if (m0 >= me) return;
    int n0 = blockIdx.x * 64;
    const int* lst = list + e * 1024;
    const float* W2 = w2 + (size_t)e * 768 * 256;

    __shared__ __align__(16) float As[16][68];
    __shared__ __align__(16) float Bs[16][68];
    __shared__ int toks[64];

    if (threadIdx.x < 64) {
        int r = m0 + threadIdx.x;
        toks[threadIdx.x] = (r < me) ? lst[r] : -1;
    }
    __syncthreads();

    int tid = threadIdx.x;
    int lk = tid & 15, lr = tid >> 4;
    int ty = tid >> 4, tx = tid & 15;
    float acc[4][4] = {};

    for (int k0 = 0; k0 < 256; k0 += 16) {
        #pragma unroll
        for (int i = 0; i < 4; i++) {
            int r = lr + i * 16;
            int ent = toks[r];
            As[lk][r] = (ent >= 0) ? g[(size_t)ent * 256 + k0 + lk] : 0.f;
            int gn = n0 + r;
            Bs[lk][r] = W2[(size_t)gn * 256 + k0 + lk];
        }
        __syncthreads();
        #pragma unroll
        for (int kk = 0; kk < 16; kk++) {
            float4 av = *reinterpret_cast<const float4*>(&As[kk][ty * 4]);
            float4 bv = *reinterpret_cast<const float4*>(&Bs[kk][tx * 4]);
            float a[4] = {av.x, av.y, av.z, av.w};
            float b[4] = {bv.x, bv.y, bv.z, bv.w};
            #pragma unroll
            for (int i = 0; i < 4; i++)
                #pragma unroll
                for (int j = 0; j < 4; j++)
                    acc[i][j] += a[i] * b[j];
        }
        __syncthreads();
    }
    #pragma unroll
    for (int i = 0; i < 4; i++) {
        int r = ty * 4 + i;
        int ent = toks[r];
        if (ent < 0) continue;
        float wgt = wts[ent];
        #pragma unroll
        for (int j = 0; j < 4; j++) {
            int n = n0 + tx * 4 + j;
            eo[(size_t)ent * 768 + n] = acc[i][j] * wgt;
        }
    }
}

// ----------------------------------------------------------------------------
// Elementwise helpers
// ----------------------------------------------------------------------------
__global__ void silu_mul_kernel(float* __restrict__ t1, const float* __restrict__ t2)
{
    int i = blockIdx.x * 256 + threadIdx.x;
    if (i < 1024 * 1024) {
        float a = t1[i];
        t1[i] = a / (1.f + expf(-a)) * t2[i];
    }
}

__global__ void moe_combine_kernel(float* __restrict__ h,
                                   const float* __restrict__ eo,
                                   const float* __restrict__ ys)
{
    int i = blockIdx.x * 256 + threadIdx.x;
    if (i < 1024 * 768) {
        int t = i / 768, c = i % 768;
        h[i] += ys[i] + eo[(size_t)(2 * t) * 768 + c] + eo[(size_t)(2 * t + 1) * 768 + c];
    }
}

// ----------------------------------------------------------------------------
// Head: out[b] = dot(xnorm[b, S-1, :], head_w) + head_b
// ----------------------------------------------------------------------------
__global__ void head_kernel(const float* __restrict__ x,
                            const float* __restrict__ hw,
                            const float* __restrict__ hb,
                            float* __restrict__ out)
{
    int b = blockIdx.x;
    const float* row = x + (size_t)(b * 512 + 511) * 768;
    __shared__ float red[256];
    float acc = 0.f;
    for (int c = threadIdx.x; c < 768; c += 256) acc += row[c] * hw[c];
    red[threadIdx.x] = acc;
    __syncthreads();
    for (int o = 128; o > 0; o >>= 1) {
        if (threadIdx.x < o) red[threadIdx.x] += red[threadIdx.x + o];
        __syncthreads();
    }
    if (threadIdx.x == 0) out[b] = red[0] + hb[0];
}

// ----------------------------------------------------------------------------
// Host launcher (graph-capturable: kernel launches only, default stream)
// ----------------------------------------------------------------------------
extern "C" void kernel_launch(void* const* d_in, const int* in_sizes, int n_in,
                              void* d_out, int out_size)
{
    const float* inputs       = (const float*)d_in[0];
    const float* in_w         = (const float*)d_in[1];
    const float* in_b         = (const float*)d_in[2];
    const float* attn_norm_w  = (const float*)d_in[3];
    const float* wq           = (const float*)d_in[4];
    const float* wkva         = (const float*)d_in[5];
    const float* kvnorm_w     = (const float*)d_in[6];
    const float* wkvb         = (const float*)d_in[7];
    const float* wo           = (const float*)d_in[8];
    const float* moe_norm_w   = (const float*)d_in[9];
    const float* gate_w       = (const float*)d_in[10];
    const float* e_w1         = (const float*)d_in[11];
    const float* e_w2         = (const float*)d_in[12];
    const float* e_w3         = (const float*)d_in[13];
    const float* s_w1         = (const float*)d_in[14];
    const float* s_w2         = (const float*)d_in[15];
    const float* s_w3         = (const float*)d_in[16];
    const float* final_norm_w = (const float*)d_in[17];
    const float* head_w       = (const float*)d_in[18];
    const float* head_b       = (const float*)d_in[19];
    float* out = (float*)d_out;

    float *h, *x, *q, *kva, *ckv, *kv, *keys, *scores, *attn, *t1, *t2, *g, *eo, *gatew;
    int *cnt, *list;
    cudaGetSymbolAddress((void**)&h,      d_h);
    cudaGetSymbolAddress((void**)&x,      d_x);
    cudaGetSymbolAddress((void**)&q,      d_q);
    cudaGetSymbolAddress((void**)&kva,    d_kva);
    cudaGetSymbolAddress((void**)&ckv,    d_ckv);
    cudaGetSymbolAddress((void**)&kv,     d_kv);
    cudaGetSymbolAddress((void**)&keys,   d_keys);
    cudaGetSymbolAddress((void**)&scores, d_scores);
    cudaGetSymbolAddress((void**)&attn,   d_attn);
    cudaGetSymbolAddress((void**)&t1,     d_t1);
    cudaGetSymbolAddress((void**)&t2,     d_t2);
    cudaGetSymbolAddress((void**)&g,      d_g);
    cudaGetSymbolAddress((void**)&eo,     d_eo);
    cudaGetSymbolAddress((void**)&gatew,  d_gatew);
    cudaGetSymbolAddress((void**)&cnt,    d_cnt);
    cudaGetSymbolAddress((void**)&list,   d_list);

    const float scale = 0.125f; // 1/sqrt(DN+DR)

    // h = inputs @ in_w.T + in_b          [1024,768] <- [1024,64]x[768,64]^T
    sgemm_nt<<<dim3(12, 16, 1), 256>>>(inputs, 64, in_w, 64, h, 768,
                                       1024, 768, 64, 1.f, 0, in_b,
                                       1, 0, 0, 0, 0, 0, 0);

    for (int l = 0; l < 12; l++) {
        const float* anw    = attn_norm_w + (size_t)l * 768;
        const float* wq_l   = wq   + (size_t)l * 768 * 768;
        const float* wkva_l = wkva + (size_t)l * 544 * 768;
        const float* kvn_l  = kvnorm_w + (size_t)l * 512;
        const float* wkvb_l = wkvb + (size_t)l * 1152 * 512;
        const float* wo_l   = wo   + (size_t)l * 768 * 768;
        const float* mnw    = moe_norm_w + (size_t)l * 768;
        const float* gw_l   = gate_w + (size_t)l * 8 * 768;
        const float* w1_l   = e_w1 + (size_t)l * 8 * 256 * 768;
        const float* w2_l   = e_w2 + (size_t)l * 8 * 768 * 256;
        const float* w3_l   = e_w3 + (size_t)l * 8 * 256 * 768;
        const float* sw1_l  = s_w1 + (size_t)l * 1024 * 768;
        const float* sw2_l  = s_w2 + (size_t)l * 768 * 1024;
        const float* sw3_l  = s_w3 + (size_t)l * 1024 * 768;

        // ---- attention ----
        rmsnorm_kernel<<<1024, 256>>>(h, 768, x, 768, 768, anw);

        sgemm_nt<<<dim3(12, 16, 1), 256>>>(x, 768, wq_l, 768, q, 768,
                                           1024, 768, 768, 1.f, 0, nullptr,
                                           1, 0, 0, 0, 0, 0, 0);
        sgemm_nt<<<dim3(9, 16, 1), 256>>>(x, 768, wkva_l, 768, kva, 544,
                                          1024, 544, 768, 1.f, 0, nullptr,
                                          1, 0, 0, 0, 0, 0, 0);
        rmsnorm_kernel<<<1024, 256>>>(kva, 544, ckv, 512, 512, kvn_l);
        sgemm_nt<<<dim3(18, 16, 1), 256>>>(ckv, 512, wkvb_l, 512, kv, 1152,
                                           1024, 1152, 512, 1.f, 0, nullptr,
                                           1, 0, 0, 0, 0, 0, 0);
        rope_keys_kernel<<<1024, 256>>>(q, kva, kv, keys);

        // scores[b,h] = scale * (q_bh @ keys_bh^T), batched over z = b*12+h
        sgemm_nt<<<dim3(8, 8, 24), 256>>>(q, 768, keys, 768, scores, 512,
                                          512, 512, 64, scale, 0, nullptr,
                                          12,
                                          512LL * 768, 64LL,
                                          512LL * 768, 64LL,
                                          12LL * 512 * 512, 512LL * 512);
        softmax_causal<<<2 * 12 * 512, 256>>>(scores);

        // attn[b,h] = probs_bh @ V_bh   (V at kv[...]+32, row stride 1152)
        sgemm_nn<<<dim3(1, 8, 24), 256>>>(scores, 512, kv + 32, 1152, attn, 768,
                                          512, 64, 512,
                                          12,
                                          12LL * 512 * 512, 512LL * 512,
                                          512LL * 1152, 96LL,
                                          512LL * 768, 64LL);

        // h += attn @ wo.T
        sgemm_nt<<<dim3(12, 16, 1), 256>>>(attn, 768, wo_l, 768, h, 768,
                                           1024, 768, 768, 1.f, 1, nullptr,
                                           1, 0, 0, 0, 0, 0, 0);

        // ---- MoE ----
        rmsnorm_kernel<<<1024, 256>>>(h, 768, x, 768, 768, mnw);

        zero_cnt_kernel<<<1, 32>>>(cnt);
        gate_kernel<<<1024, 256>>>(x, gw_l, cnt, list, gatew);

        expert_mlp1<<<dim3(4, 16, 8), 256>>>(x, w1_l, w3_l, cnt, list, g);
        expert_mlp2<<<dim3(12, 16, 8), 256>>>(g, w2_l, cnt, list, gatew, eo);

        // shared expert: t1 = x@sw1.T, t2 = x@sw3.T, t1 = silu(t1)*t2, ys(t2) = t1@sw2.T
        sgemm_nt<<<dim3(16, 16, 1), 256>>>(x, 768, sw1_l, 768, t1, 1024,
                                           1024, 1024, 768, 1.f, 0, nullptr,
                                           1, 0, 0, 0, 0, 0, 0);
        sgemm_nt<<<dim3(16, 16, 1), 256>>>(x, 768, sw3_l, 768, t2, 1024,
                                           1024, 1024, 768, 1.f, 0, nullptr,
                                           1, 0, 0, 0, 0, 0, 0);
        silu_mul_kernel<<<4096, 256>>>(t1, t2);
        sgemm_nt<<<dim3(12, 16, 1), 256>>>(t1, 1024, sw2_l, 1024, t2, 768,
                                           1024, 768, 1024, 1.f, 0, nullptr,
                                           1, 0, 0, 0, 0, 0, 0);

        moe_combine_kernel<<<3072, 256>>>(h, eo, t2);
    }

    rmsnorm_kernel<<<1024, 256>>>(h, 768, x, 768, 768, final_norm_w);
    head_kernel<<<2, 256>>>(x, head_w, head_b, out);
}

// round 17
// speedup vs baseline: 1.0901x; 1.0901x over previous
#include <cuda_runtime.h>
#include <cmath>

// ----------------------------------------------------------------------------
// Model dims
//   L=12, H=768, NH=12, DN=32, DR=32, DV=64, R=512, E=8, K=2, I=256, SI=1024
//   B=2, S=512, V=64  -> T = B*S = 1024 tokens
// ----------------------------------------------------------------------------

// ---------------- device scratch (static, allocation-free) ----------------
__device__ float d_h   [1024*768];        // residual stream
__device__ float d_x   [1024*768];        // rms-normed activations
__device__ float d_q   [1024*768];        // q per token: [h][64] (nope||pe)
__device__ float d_kva [1024*544];        // c_kv(512) || k_pe(32)
__device__ float d_ckv [1024*512];        // normed c_kv
__device__ float d_kv  [1024*1152];       // per token: [h][96] (k_nope(32)||v(64))
__device__ float d_keys[1024*768];        // per token: [h][64] (k_nope||roped k_pe)
__device__ float d_scores[2*12*512*512];  // [b][h][q][k]
__device__ float d_attn[1024*768];        // [t][h*64+dv]
__device__ float d_t1  [1024*1024];       // shared-FFN silu(x@w1^T)*(x@w3^T)
__device__ float d_t2  [1024*768];        // shared-FFN output ys
__device__ float d_g   [2048*256];        // expert hidden per token-slot
__device__ float d_eo  [2048*768];        // expert output per token-slot (pre-weighted)
__device__ float d_gatew[2048];           // normalized top-2 weights per token-slot
__device__ int   d_cnt [8];
__device__ int   d_list[8*1024];          // per-expert: entry = token*2 + slot

// ----------------------------------------------------------------------------
// Pipelined NT SGEMM:  C[m,n] (=, +=) alpha * sum_k A[m,k]*B[n,k]  (+ bias[n])
// 64x64 tile, TK=16, 256 threads, 4x4 per thread, double-buffered smem with
// register prefetch (one __syncthreads per k-tile). K must be a multiple of 16.
// Batched via blockIdx.z decoded as (bb = z/zdiv, hh = z%zdiv) with strides.
// ----------------------------------------------------------------------------
__global__ void sgemm_nt(const float* __restrict__ A, int lda,
                         const float* __restrict__ B, int ldb,
                         float* __restrict__ C, int ldc,
                         int M, int N, int K, float alpha, int mode,
                         const float* __restrict__ bias,
                         int zdiv, long long sAb, long long sAh,
                         long long sBb, long long sBh,
                         long long sCb, long long sCh)
{
    int z = blockIdx.z;
    int bb = z / zdiv, hh = z % zdiv;
    A += bb * sAb + hh * sAh;
    B += bb * sBb + hh * sBh;
    C += bb * sCb + hh * sCh;

    __shared__ __align__(16) float As[2][16][68];
    __shared__ __align__(16) float Bs[2][16][68];

    int n0 = blockIdx.x * 64, m0 = blockIdx.y * 64;
    int tid = threadIdx.x;
    int lk = tid & 15, lr = tid >> 4;
    int ty = tid >> 4, tx = tid & 15;

    float ra[4], rb[4];
    #pragma unroll
    for (int i = 0; i < 4; i++) {
        int r = lr + i * 16;
        int gm = m0 + r, gn = n0 + r;
        ra[i] = (gm < M) ? A[(size_t)gm * lda + lk] : 0.f;
        rb[i] = (gn < N) ? B[(size_t)gn * ldb + lk] : 0.f;
    }
    #pragma unroll
    for (int i = 0; i < 4; i++) {
        As[0][lk][lr + i * 16] = ra[i];
        Bs[0][lk][lr + i * 16] = rb[i];
    }
    __syncthreads();

    float acc[4][4] = {};
    int buf = 0;
    for (int k0 = 16; k0 < K; k0 += 16) {
        // prefetch next tile into registers (latency hidden by compute below)
        #pragma unroll
        for (int i = 0; i < 4; i++) {
            int r = lr + i * 16;
            int gm = m0 + r, gn = n0 + r;
            ra[i] = (gm < M) ? A[(size_t)gm * lda + k0 + lk] : 0.f;
            rb[i] = (gn < N) ? B[(size_t)gn * ldb + k0 + lk] : 0.f;
        }
        // compute current tile
        #pragma unroll
        for (int kk = 0; kk < 16; kk++) {
            float4 av = *reinterpret_cast<const float4*>(&As[buf][kk][ty * 4]);
            float4 bv = *reinterpret_cast<const float4*>(&Bs[buf][kk][tx * 4]);
            float a[4] = {av.x, av.y, av.z, av.w};
            float b[4] = {bv.x, bv.y, bv.z, bv.w};
            #pragma unroll
            for (int i = 0; i < 4; i++)
                #pragma unroll
                for (int j = 0; j < 4; j++)
                    acc[i][j] += a[i] * b[j];
        }
        // commit prefetched tile to the other buffer
        #pragma unroll
        for (int i = 0; i < 4; i++) {
            As[buf ^ 1][lk][lr + i * 16] = ra[i];
            Bs[buf ^ 1][lk][lr + i * 16] = rb[i];
        }
        __syncthreads();
        buf ^= 1;
    }
    // last tile
    #pragma unroll
    for (int kk = 0; kk < 16; kk++) {
        float4 av = *reinterpret_cast<const float4*>(&As[buf][kk][ty * 4]);
        float4 bv = *reinterpret_cast<const float4*>(&Bs[buf][kk][tx * 4]);
        float a[4] = {av.x, av.y, av.z, av.w};
        float b[4] = {bv.x, bv.y, bv.z, bv.w};
        #pragma unroll
        for (int i = 0; i < 4; i++)
            #pragma unroll
            for (int j = 0; j < 4; j++)
                acc[i][j] += a[i] * b[j];
    }

    #pragma unroll
    for (int i = 0; i < 4; i++) {
        int m = m0 + ty * 4 + i;
        if (m >= M) continue;
        #pragma unroll
        for (int j = 0; j < 4; j++) {
            int n = n0 + tx * 4 + j;
            if (n >= N) continue;
            float v = acc[i][j] * alpha;
            if (bias) v += bias[n];
            if (mode) C[(size_t)m * ldc + n] += v;
            else      C[(size_t)m * ldc + n]  = v;
        }
    }
}

// ----------------------------------------------------------------------------
// Pipelined NN SGEMM:  C[m,n] = sum_k A[m,k]*B[k,n]   (used for probs @ V)
// ----------------------------------------------------------------------------
__global__ void sgemm_nn(const float* __restrict__ A, int lda,
                         const float* __restrict__ B, int ldb,
                         float* __restrict__ C, int ldc,
                         int M, int N, int K,
                         int zdiv, long long sAb, long long sAh,
                         long long sBb, long long sBh,
                         long long sCb, long long sCh)
{
    int z = blockIdx.z;
    int bb = z / zdiv, hh = z % zdiv;
    A += bb * sAb + hh * sAh;
    B += bb * sBb + hh * sBh;
    C += bb * sCb + hh * sCh;

    __shared__ __align__(16) float As[2][16][68];
    __shared__ __align__(16) float Bs[2][16][68];

    int n0 = blockIdx.x * 64, m0 = blockIdx.y * 64;
    int tid = threadIdx.x;
    int lk = tid & 15, lr = tid >> 4;
    int bc = tid & 63, bk = tid >> 6;
    int ty = tid >> 4, tx = tid & 15;

    float ra[4], rb[4];
    {
        int gn = n0 + bc;
        #pragma unroll
        for (int i = 0; i < 4; i++) {
            int r = lr + i * 16;
            int gm = m0 + r;
            ra[i] = (gm < M) ? A[(size_t)gm * lda + lk] : 0.f;
            int kk = bk + i * 4;
            rb[i] = (gn < N) ? B[(size_t)kk * ldb + gn] : 0.f;
        }
    }
    #pragma unroll
    for (int i = 0; i < 4; i++) {
        As[0][lk][lr + i * 16] = ra[i];
        Bs[0][bk + i * 4][bc] = rb[i];
    }
    __syncthreads();

    float acc[4][4] = {};
    int buf = 0;
    for (int k0 = 16; k0 < K; k0 += 16) {
        {
            int gn = n0 + bc;
            #pragma unroll
            for (int i = 0; i < 4; i++) {
                int r = lr + i * 16;
                int gm = m0 + r;
                ra[i] = (gm < M) ? A[(size_t)gm * lda + k0 + lk] : 0.f;
                int kk = bk + i * 4;
                rb[i] = (gn < N) ? B[(size_t)(k0 + kk) * ldb + gn] : 0.f;
            }
        }
        #pragma unroll
        for (int kk = 0; kk < 16; kk++) {
            float4 av = *reinterpret_cast<const float4*>(&As[buf][kk][ty * 4]);
            float4 bv = *reinterpret_cast<const float4*>(&Bs[buf][kk][tx * 4]);
            float a[4] = {av.x, av.y, av.z, av.w};
            float b[4] = {bv.x, bv.y, bv.z, bv.w};
            #pragma unroll
            for (int i = 0; i < 4; i++)
                #pragma unroll
                for (int j = 0; j < 4; j++)
                    acc[i][j] += a[i] * b[j];
        }
        #pragma unroll
        for (int i = 0; i < 4; i++) {
            As[buf ^ 1][lk][lr + i * 16] = ra[i];
            Bs[buf ^ 1][bk + i * 4][bc] = rb[i];
        }
        __syncthreads();
        buf ^= 1;
    }
    #pragma unroll
    for (int kk = 0; kk < 16; kk++) {
        float4 av = *reinterpret_cast<const float4*>(&As[buf][kk][ty * 4]);
        float4 bv = *reinterpret_cast<const float4*>(&Bs[buf][kk][tx * 4]);
        float a[4] = {av.x, av.y, av.z, av.w};
        float b[4] = {bv.x, bv.y, bv.z, bv.w};
        #pragma unroll
        for (int i = 0; i < 4; i++)
            #pragma unroll
            for (int j = 0; j < 4; j++)
                acc[i][j] += a[i] * b[j];
    }

    #pragma unroll
    for (int i = 0; i < 4; i++) {
        int m = m0 + ty * 4 + i;
        if (m >= M) continue;
        #pragma unroll
        for (int j = 0; j < 4; j++) {
            int n = n0 + tx * 4 + j;
            if (n >= N) continue;
            C[(size_t)m * ldc + n] = acc[i][j];
        }
    }
}

// ----------------------------------------------------------------------------
// Fused shared-FFN stage 1 (pipelined dual NT GEMM + silu-mul epilogue):
//   g[m, n] = silu(x[m]@w1[n].T) * (x[m]@w3[n].T),  M=1024, N=1024, K=768
// ----------------------------------------------------------------------------
__global__ void ffn_dual(const float* __restrict__ x,
                         const float* __restrict__ w1,
                         const float* __restrict__ w3,
                         float* __restrict__ g,
                         int M, int N, int K)
{
    __shared__ __align__(16) float As[2][16][68];
    __shared__ __align__(16) float B1[2][16][68];
    __shared__ __align__(16) float B3[2][16][68];

    int n0 = blockIdx.x * 64, m0 = blockIdx.y * 64;
    int tid = threadIdx.x;
    int lk = tid & 15, lr = tid >> 4;
    int ty = tid >> 4, tx = tid & 15;

    float ra[4], r1[4], r3[4];
    #pragma unroll
    for (int i = 0; i < 4; i++) {
        int r = lr + i * 16;
        int gm = m0 + r, gn = n0 + r;
        ra[i] = (gm < M) ? x [(size_t)gm * K + lk] : 0.f;
        r1[i] = (gn < N) ? w1[(size_t)gn * K + lk] : 0.f;
        r3[i] = (gn < N) ? w3[(size_t)gn * K + lk] : 0.f;
    }
    #pragma unroll
    for (int i = 0; i < 4; i++) {
        int r = lr + i * 16;
        As[0][lk][r] = ra[i]; B1[0][lk][r] = r1[i]; B3[0][lk][r] = r3[i];
    }
    __syncthreads();

    float a1[4][4] = {}, a3[4][4] = {};
    int buf = 0;
    for (int k0 = 16; k0 < K; k0 += 16) {
        #pragma unroll
        for (int i = 0; i < 4; i++) {
            int r = lr + i * 16;
            int gm = m0 + r, gn = n0 + r;
            ra[i] = (gm < M) ? x [(size_t)gm * K + k0 + lk] : 0.f;
            r1[i] = (gn < N) ? w1[(size_t)gn * K + k0 + lk] : 0.f;
            r3[i] = (gn < N) ? w3[(size_t)gn * K + k0 + lk] : 0.f;
        }
        #pragma unroll
        for (int kk = 0; kk < 16; kk++) {
            float4 av  = *reinterpret_cast<const float4*>(&As[buf][kk][ty * 4]);
            float4 b1v = *reinterpret_cast<const float4*>(&B1[buf][kk][tx * 4]);
            float4 b3v = *reinterpret_cast<const float4*>(&B3[buf][kk][tx * 4]);
            float a[4]  = {av.x,  av.y,  av.z,  av.w};
            float b1[4] = {b1v.x, b1v.y, b1v.z, b1v.w};
            float b3[4] = {b3v.x, b3v.y, b3v.z, b3v.w};
            #pragma unroll
            for (int i = 0; i < 4; i++)
                #pragma unroll
                for (int j = 0; j < 4; j++) {
                    a1[i][j] += a[i] * b1[j];
                    a3[i][j] += a[i] * b3[j];
                }
        }
        #pragma unroll
        for (int i = 0; i < 4; i++) {
            int r = lr + i * 16;
            As[buf ^ 1][lk][r] = ra[i];
            B1[buf ^ 1][lk][r] = r1[i];
            B3[buf ^ 1][lk][r] = r3[i];
        }
        __syncthreads();
        buf ^= 1;
    }
    #pragma unroll
    for (int kk = 0; kk < 16; kk++) {
        float4 av  = *reinterpret_cast<const float4*>(&As[buf][kk][ty * 4]);
        float4 b1v = *reinterpret_cast<const float4*>(&B1[buf][kk][tx * 4]);
        float4 b3v = *reinterpret_cast<const float4*>(&B3[buf][kk][tx * 4]);
        float a[4]  = {av.x,  av.y,  av.z,  av.w};
        float b1[4] = {b1v.x, b1v.y, b1v.z, b1v.w};
        float b3[4] = {b3v.x, b3v.y, b3v.z, b3v.w};
        #pragma unroll
        for (int i = 0; i < 4; i++)
            #pragma unroll
            for (int j = 0; j < 4; j++) {
                a1[i][j] += a[i] * b1[j];
                a3[i][j] += a[i] * b3[j];
            }
    }

    #pragma unroll
    for (int i = 0; i < 4; i++) {
        int m = m0 + ty * 4 + i;
        if (m >= M) continue;
        #pragma unroll
        for (int j = 0; j < 4; j++) {
            int n = n0 + tx * 4 + j;
            if (n >= N) continue;
            float va = a1[i][j];
            float sv = va / (1.f + expf(-va));
            g[(size_t)m * N + n] = sv * a3[i][j];
        }
    }
}

// ----------------------------------------------------------------------------
// RMSNorm: out[t, 0..w) = in[t]/sqrt(mean(in^2)+1e-6) * weight
// ----------------------------------------------------------------------------
__global__ void rmsnorm_kernel(const float* __restrict__ in, int istride,
                               float* __restrict__ out, int ostride,
                               int width, const float* __restrict__ w)
{
    int t = blockIdx.x;
    const float* xi = in + (size_t)t * istride;
    float* xo = out + (size_t)t * ostride;
    __shared__ float red[256];
    float ss = 0.f;
    for (int c = threadIdx.x; c < width; c += 256) { float v = xi[c]; ss += v * v; }
    red[threadIdx.x] = ss;
    __syncthreads();
    for (int o = 128; o > 0; o >>= 1) {
        if (threadIdx.x < o) red[threadIdx.x] += red[threadIdx.x + o];
        __syncthreads();
    }
    float inv = 1.f / sqrtf(red[0] / (float)width + 1e-6f);
    for (int c = threadIdx.x; c < width; c += 256)
        xo[c] = xi[c] * inv * w[c];
}

// ----------------------------------------------------------------------------
// RoPE (q in-place) + build keys buffer [t][h][ k_nope(32) || roped k_pe(32) ]
// inv_freq[d] = 10000^(-d/32), rot_half over halves of 16.
// POSITION is the within-batch sequence index: pos = t % 512 (t = b*512 + s).
// ----------------------------------------------------------------------------
__global__ void rope_keys_kernel(float* __restrict__ q,
                                 const float* __restrict__ kva,
                                 const float* __restrict__ kv,
                                 float* __restrict__ keys)
{
    int t = blockIdx.x;
    int pos = t & 511;   // sequence position within the batch (B=2, S=512)
    __shared__ float cs[32], sn[32], kr[32];
    if (threadIdx.x < 32) {
        int d = threadIdx.x;
        double f = pow(10000.0, -(double)d / 32.0);
        double ang = (double)pos * f;
        cs[d] = (float)cos(ang);
        sn[d] = (float)sin(ang);
    }
    __syncthreads();
    if (threadIdx.x < 32) {
        int d = threadIdx.x;
        const float* kp = kva + (size_t)t * 544 + 512;
        float rot = (d < 16) ? -kp[d + 16] : kp[d - 16];
        kr[d] = kp[d] * cs[d] + rot * sn[d];
    }
    if (threadIdx.x < 192) {
        int h = threadIdx.x / 16, d = threadIdx.x % 16;
        float* qp = q + (size_t)t * 768 + h * 64 + 32;
        float a = qp[d], b = qp[d + 16];
        qp[d]      = a * cs[d]      - b * sn[d];
        qp[d + 16] = b * cs[d + 16] + a * sn[d + 16];
    }
    __syncthreads();
    for (int i = threadIdx.x; i < 768; i += 256) {
        int h = i >> 6, d = i & 63;
        keys[(size_t)t * 768 + i] =
            (d < 32) ? kv[(size_t)t * 1152 + h * 96 + d] : kr[d - 32];
    }
}

// ----------------------------------------------------------------------------
// Causal row softmax over materialized scores. row = ((b*12+h)*512 + q)
// ----------------------------------------------------------------------------
__global__ void softmax_causal(float* __restrict__ sc)
{
    long long row = blockIdx.x;
    int q = (int)(row & 511);
    float* s = sc + row * 512;
    __shared__ float red[256];
    float mx = -3.4e38f;
    for (int k = threadIdx.x; k <= q; k += 256) mx = fmaxf(mx, s[k]);
    red[threadIdx.x] = mx;
    __syncthreads();
    for (int o = 128; o > 0; o >>= 1) {
        if (threadIdx.x < o) red[threadIdx.x] = fmaxf(red[threadIdx.x], red[threadIdx.x + o]);
        __syncthreads();
    }
    mx = red[0];
    __syncthreads();
    float sum = 0.f;
    for (int k = threadIdx.x; k <= q; k += 256) {
        float e = expf(s[k] - mx);
        s[k] = e;
        sum += e;
    }
    red[threadIdx.x] = sum;
    __syncthreads();
    for (int o = 128; o > 0; o >>= 1) {
        if (threadIdx.x < o) red[threadIdx.x] += red[threadIdx.x + o];
        __syncthreads();
    }
    float inv = 1.f / red[0];
    for (int k = threadIdx.x; k < 512; k += 256)
        s[k] = (k <= q) ? s[k] * inv : 0.f;
}

// ----------------------------------------------------------------------------
// Gate: logits = x @ gw.T (8), top-2, normalized weights, per-expert lists.
// softmax normalization cancels in topv/sum(topv) -> compute from logits.
// ----------------------------------------------------------------------------
__global__ void gate_kernel(const float* __restrict__ x,
                            const float* __restrict__ gw,
                            int* __restrict__ cnt, int* __restrict__ list,
                            float* __restrict__ wts)
{
    int t = blockIdx.x;
    __shared__ float xs[768];
    __shared__ float logits[8];
    for (int c = threadIdx.x; c < 768; c += 256) xs[c] = x[(size_t)t * 768 + c];
    __syncthreads();
    int warp = threadIdx.x >> 5, lane = threadIdx.x & 31;
    float acc = 0.f;
    for (int c = lane; c < 768; c += 32) acc += xs[c] * gw[warp * 768 + c];
    for (int o = 16; o > 0; o >>= 1) acc += __shfl_down_sync(0xffffffffu, acc, o);
    if (lane == 0) logits[warp] = acc;
    __syncthreads();
    if (threadIdx.x == 0) {
        int i0 = 0;
        for (int e = 1; e < 8; e++) if (logits[e] > logits[i0]) i0 = e;
        int i1 = (i0 == 0) ? 1 : 0;
        for (int e = 0; e < 8; e++) {
            if (e == i0) continue;
            if (logits[e] > logits[i1]) i1 = e;
        }
        float p0 = 1.f;                       // exp(l0 - l0)
        float p1 = expf(logits[i1] - logits[i0]);
        float s = p0 + p1;
        int pos0 = atomicAdd(&cnt[i0], 1);
        list[i0 * 1024 + pos0] = t * 2 + 0;
        wts[t * 2 + 0] = p0 / s;
        int pos1 = atomicAdd(&cnt[i1], 1);
        list[i1 * 1024 + pos1] = t * 2 + 1;
        wts[t * 2 + 1] = p1 / s;
    }
}

__global__ void zero_cnt_kernel(int* __restrict__ cnt)
{
    if (threadIdx.x < 8) cnt[threadIdx.x] = 0;
}

// ----------------------------------------------------------------------------
// Expert MLP stage 1 (dual gathered NT GEMM + silu-mul epilogue):
//   g[entry, n] = silu(x[tok]@w1[e].T) * (x[tok]@w3[e].T),  K=768, N=256
// ----------------------------------------------------------------------------
__global__ void expert_mlp1(const float* __restrict__ x,
                            const float* __restrict__ w1,
                            const float* __restrict__ w3,
                            const int* __restrict__ cnt,
                            const int* __restrict__ list,
                            float* __restrict__ g)
{
    int e = blockIdx.z;
    int me = cnt[e];
    int m0 = blockIdx.y * 64;
    if (m0 >= me) return;
    int n0 = blockIdx.x * 64;
    const int* lst = list + e * 1024;
    const float* W1 = w1 + (size_t)e * 256 * 768;
    const float* W3 = w3 + (size_t)e * 256 * 768;

    __shared__ __align__(16) float As[16][68];
    __shared__ __align__(16) float B1[16][68];
    __shared__ __align__(16) float B3[16][68];
    __shared__ int toks[64];

    if (threadIdx.x < 64) {
        int r = m0 + threadIdx.x;
        toks[threadIdx.x] = (r < me) ? lst[r] : -1;
    }
    __syncthreads();

    int tid = threadIdx.x;
    int lk = tid & 15, lr = tid >> 4;
    int ty = tid >> 4, tx = tid & 15;
    float a1[4][4] = {}, a3[4][4] = {};

    for (int k0 = 0; k0 < 768; k0 += 16) {
        #pragma unroll
        for (int i = 0; i < 4; i++) {
            int r = lr + i * 16;
            int ent = toks[r];
            As[lk][r] = (ent >= 0) ? x[(size_t)(ent >> 1) * 768 + k0 + lk] : 0.f;
            int gn = n0 + r;
            B1[lk][r] = W1[(size_t)gn * 768 + k0 + lk];
            B3[lk][r] = W3[(size_t)gn * 768 + k0 + lk];
        }
        __syncthreads();
        #pragma unroll
        for (int kk = 0; kk < 16; kk++) {
            float4 av  = *reinterpret_cast<const float4*>(&As[kk][ty * 4]);
            float4 b1v = *reinterpret_cast<const float4*>(&B1[kk][tx * 4]);
            float4 b3v = *reinterpret_cast<const float4*>(&B3[kk][tx * 4]);
            float a[4]  = {av.x,  av.y,  av.z,  av.w};
            float b1[4] = {b1v.x, b1v.y, b1v.z, b1v.w};
            float b3[4] = {b3v.x, b3v.y, b3v.z, b3v.w};
            #pragma unroll
            for (int i = 0; i < 4; i++)
                #pragma unroll
                for (int j = 0; j < 4; j++) {
                    a1[i][j] += a[i] * b1[j];
                    a3[i][j] += a[i] * b3[j];
                }
        }
        __syncthreads();
    }
    #pragma unroll
    for (int i = 0; i < 4; i++) {
        int r = ty * 4 + i;
        int ent = toks[r];
        if (ent < 0) continue;
        #pragma unroll
        for (int j = 0; j < 4; j++) {
            int n = n0 + tx * 4 + j;
            float va = a1[i][j];
            float sv = va / (1.f + expf(-va));
            g[(size_t)ent * 256 + n] = sv * a3[i][j];
        }
    }
}

// ----------------------------------------------------------------------------
// Expert MLP stage 2 (gathered NT GEMM, weighted scatter):
//   eo[entry, n] = wts[entry] * (g[entry]@w2[e].T),  K=256, N=768
// ----------------------------------------------------------------------------
__global__ void expert_mlp2(const float* __restrict__ g,
                            const float* __restrict__ w2,
                            const int* __restrict__ cnt,
                            const int* __restrict__ list,
                            const float* __restrict__ wts,
                            float* __restrict__ eo)
{
    int e = blockIdx.z;
    int me = cnt[e];
    int m0 = blockIdx.y * 64;
    if (m0 >= me) return;
    int n0 = blockIdx.x * 64;
    const int* lst = list + e * 1024;
    const float* W2 = w2 + (size_t)e * 768 * 256;

    __shared__ __align__(16) float As[16][68];
    __shared__ __align__(16) float Bs[16][68];
    __shared__ int toks[64];

    if (threadIdx.x < 64) {
        int r = m0 + threadIdx.x;
        toks[threadIdx.x] = (r < me) ? lst[r] : -1;
    }
    __syncthreads();

    int tid = threadIdx.x;
    int lk = tid & 15, lr = tid >> 4;
    int ty = tid >> 4, tx = tid & 15;
    float acc[4][4] = {};

    for (int k0 = 0; k0 < 256; k0 += 16) {
        #pragma unroll
        for (int i = 0; i < 4; i++) {
            int r = lr + i * 16;
            int ent = toks[r];
            As[lk][r] = (ent >= 0) ? g[(size_t)ent * 256 + k0 + lk] : 0.f;
            int gn = n0 + r;
            Bs[lk][r] = W2[(size_t)gn * 256 + k0 + lk];
        }
        __syncthreads();
        #pragma unroll
        for (int kk = 0; kk < 16; kk++) {
            float4 av = *reinterpret_cast<const float4*>(&As[kk][ty * 4]);
            float4 bv = *reinterpret_cast<const float4*>(&Bs[kk][tx * 4]);
            float a[4] = {av.x, av.y, av.z, av.w};
            float b[4] = {bv.x, bv.y, bv.z, bv.w};
            #pragma unroll
            for (int i = 0; i < 4; i++)
                #pragma unroll
                for (int j = 0; j < 4; j++)
                    acc[i][j] += a[i] * b[j];
        }
        __syncthreads();
    }
    #pragma unroll
    for (int i = 0; i < 4; i++) {
        int r = ty * 4 + i;
        int ent = toks[r];
        if (ent < 0) continue;
        float wgt = wts[ent];
        #pragma unroll
        for (int j = 0; j < 4; j++) {
            int n = n0 + tx * 4 + j;
            eo[(size_t)ent * 768 + n] = acc[i][j] * wgt;
        }
    }
}

// ----------------------------------------------------------------------------
// Combine: h += ys + eo[slot0] + eo[slot1]
// ----------------------------------------------------------------------------
__global__ void moe_combine_kernel(float* __restrict__ h,
                                   const float* __restrict__ eo,
                                   const float* __restrict__ ys)
{
    int i = blockIdx.x * 256 + threadIdx.x;
    if (i < 1024 * 768) {
        int t = i / 768, c = i % 768;
        h[i] += ys[i] + eo[(size_t)(2 * t) * 768 + c] + eo[(size_t)(2 * t + 1) * 768 + c];
    }
}

// ----------------------------------------------------------------------------
// Head: out[b] = dot(xnorm[b, S-1, :], head_w) + head_b
// ----------------------------------------------------------------------------
__global__ void head_kernel(const float* __restrict__ x,
                            const float* __restrict__ hw,
                            const float* __restrict__ hb,
                            float* __restrict__ out)
{
    int b = blockIdx.x;
    const float* row = x + (size_t)(b * 512 + 511) * 768;
    __shared__ float red[256];
    float acc = 0.f;
    for (int c = threadIdx.x; c < 768; c += 256) acc += row[c] * hw[c];
    red[threadIdx.x] = acc;
    __syncthreads();
    for (int o = 128; o > 0; o >>= 1) {
        if (threadIdx.x < o) red[threadIdx.x] += red[threadIdx.x + o];
        __syncthreads();
    }
    if (threadIdx.x == 0) out[b] = red[0] + hb[0];
}

// ----------------------------------------------------------------------------
// Host launcher (graph-capturable: kernel launches only, default stream)
// ----------------------------------------------------------------------------
extern "C" void kernel_launch(void* const* d_in, const int* in_sizes, int n_in,
                              void* d_out, int out_size)
{
    const float* inputs       = (const float*)d_in[0];
    const float* in_w         = (const float*)d_in[1];
    const float* in_b         = (const float*)d_in[2];
    const float* attn_norm_w  = (const float*)d_in[3];
    const float* wq           = (const float*)d_in[4];
    const float* wkva         = (const float*)d_in[5];
    const float* kvnorm_w     = (const float*)d_in[6];
    const float* wkvb         = (const float*)d_in[7];
    const float* wo           = (const float*)d_in[8];
    const float* moe_norm_w   = (const float*)d_in[9];
    const float* gate_w       = (const float*)d_in[10];
    const float* e_w1         = (const float*)d_in[11];
    const float* e_w2         = (const float*)d_in[12];
    const float* e_w3         = (const float*)d_in[13];
    const float* s_w1         = (const float*)d_in[14];
    const float* s_w2         = (const float*)d_in[15];
    const float* s_w3         = (const float*)d_in[16];
    const float* final_norm_w = (const float*)d_in[17];
    const float* head_w       = (const float*)d_in[18];
    const float* head_b       = (const float*)d_in[19];
    float* out = (float*)d_out;

    float *h, *x, *q, *kva, *ckv, *kv, *keys, *scores, *attn, *t1, *t2, *g, *eo, *gatew;
    int *cnt, *list;
    cudaGetSymbolAddress((void**)&h,      d_h);
    cudaGetSymbolAddress((void**)&x,      d_x);
    cudaGetSymbolAddress((void**)&q,      d_q);
    cudaGetSymbolAddress((void**)&kva,    d_kva);
    cudaGetSymbolAddress((void**)&ckv,    d_ckv);
    cudaGetSymbolAddress((void**)&kv,     d_kv);
    cudaGetSymbolAddress((void**)&keys,   d_keys);
    cudaGetSymbolAddress((void**)&scores, d_scores);
    cudaGetSymbolAddress((void**)&attn,   d_attn);
    cudaGetSymbolAddress((void**)&t1,     d_t1);
    cudaGetSymbolAddress((void**)&t2,     d_t2);
    cudaGetSymbolAddress((void**)&g,      d_g);
    cudaGetSymbolAddress((void**)&eo,     d_eo);
    cudaGetSymbolAddress((void**)&gatew,  d_gatew);
    cudaGetSymbolAddress((void**)&cnt,    d_cnt);
    cudaGetSymbolAddress((void**)&list,   d_list);

    const float scale = 0.125f; // 1/sqrt(DN+DR)

    // h = inputs @ in_w.T + in_b          [1024,768] <- [1024,64]x[768,64]^T
    sgemm_nt<<<dim3(12, 16, 1), 256>>>(inputs, 64, in_w, 64, h, 768,
                                       1024, 768, 64, 1.f, 0, in_b,
                                       1, 0, 0, 0, 0, 0, 0);

    for (int l = 0; l < 12; l++) {
        const float* anw    = attn_norm_w + (size_t)l * 768;
        const float* wq_l   = wq   + (size_t)l * 768 * 768;
        const float* wkva_l = wkva + (size_t)l * 544 * 768;
        const float* kvn_l  = kvnorm_w + (size_t)l * 512;
        const float* wkvb_l = wkvb + (size_t)l * 1152 * 512;
        const float* wo_l   = wo   + (size_t)l * 768 * 768;
        const float* mnw    = moe_norm_w + (size_t)l * 768;
        const float* gw_l   = gate_w + (size_t)l * 8 * 768;
        const float* w1_l   = e_w1 + (size_t)l * 8 * 256 * 768;
        const float* w2_l   = e_w2 + (size_t)l * 8 * 768 * 256;
        const float* w3_l   = e_w3 + (size_t)l * 8 * 256 * 768;
        const float* sw1_l  = s_w1 + (size_t)l * 1024 * 768;
        const float* sw2_l  = s_w2 + (size_t)l * 768 * 1024;
        const float* sw3_l  = s_w3 + (size_t)l * 1024 * 768;

        // ---- attention ----
        rmsnorm_kernel<<<1024, 256>>>(h, 768, x, 768, 768, anw);

        sgemm_nt<<<dim3(12, 16, 1), 256>>>(x, 768, wq_l, 768, q, 768,
                                           1024, 768, 768, 1.f, 0, nullptr,
                                           1, 0, 0, 0, 0, 0, 0);
        sgemm_nt<<<dim3(9, 16, 1), 256>>>(x, 768, wkva_l, 768, kva, 544,
                                          1024, 544, 768, 1.f, 0, nullptr,
                                          1, 0, 0, 0, 0, 0, 0);
        rmsnorm_kernel<<<1024, 256>>>(kva, 544, ckv, 512, 512, kvn_l);
        sgemm_nt<<<dim3(18, 16, 1), 256>>>(ckv, 512, wkvb_l, 512, kv, 1152,
                                           1024, 1152, 512, 1.f, 0, nullptr,
                                           1, 0, 0, 0, 0, 0, 0);
        rope_keys_kernel<<<1024, 256>>>(q, kva, kv, keys);

        // scores[b,h] = scale * (q_bh @ keys_bh^T), batched over z = b*12+h
        sgemm_nt<<<dim3(8, 8, 24), 256>>>(q, 768, keys, 768, scores, 512,
                                          512, 512, 64, scale, 0, nullptr,
                                          12,
                                          512LL * 768, 64LL,
                                          512LL * 768, 64LL,
                                          12LL * 512 * 512, 512LL * 512);
        softmax_causal<<<2 * 12 * 512, 256>>>(scores);

        // attn[b,h] = probs_bh @ V_bh   (V at kv[...]+32, row stride 1152)
        sgemm_nn<<<dim3(1, 8, 24), 256>>>(scores, 512, kv + 32, 1152, attn, 768,
                                          512, 64, 512,
                                          12,
                                          12LL * 512 * 512, 512LL * 512,
                                          512LL * 1152, 96LL,
                                          512LL * 768, 64LL);

        // h += attn @ wo.T
        sgemm_nt<<<dim3(12, 16, 1), 256>>>(attn, 768, wo_l, 768, h, 768,
                                           1024, 768, 768, 1.f, 1, nullptr,
                                           1, 0, 0, 0, 0, 0, 0);

        // ---- MoE ----
        rmsnorm_kernel<<<1024, 256>>>(h, 768, x, 768, 768, mnw);

        zero_cnt_kernel<<<1, 32>>>(cnt);
        gate_kernel<<<1024, 256>>>(x, gw_l, cnt, list, gatew);

        expert_mlp1<<<dim3(4, 16, 8), 256>>>(x, w1_l, w3_l, cnt, list, g);
        expert_mlp2<<<dim3(12, 16, 8), 256>>>(g, w2_l, cnt, list, gatew, eo);

        // shared expert: t1 = silu(x@sw1.T)*(x@sw3.T)  (fused dual GEMM)
        ffn_dual<<<dim3(16, 16, 1), 256>>>(x, sw1_l, sw3_l, t1, 1024, 1024, 768);
        // ys(t2) = t1 @ sw2.T
        sgemm_nt<<<dim3(12, 16, 1), 256>>>(t1, 1024, sw2_l, 1024, t2, 768,
                                           1024, 768, 1024, 1.f, 0, nullptr,
                                           1, 0, 0, 0, 0, 0, 0);

        moe_combine_kernel<<<3072, 256>>>(h, eo, t2);
    }

    rmsnorm_kernel<<<1024, 256>>>(h, 768, x, 768, 768, final_norm_w);
    head_kernel<<<2, 256>>>(x, head_w, head_b, out);
}